// round 17
// baseline (speedup 1.0000x reference)
#include <cuda_runtime.h>
#include <cuda_bf16.h>
#include <math.h>

// Problem constants
#define B_SZ   1024
#define LU     200
#define LH     50
#define D_SZ   768
#define XCOLS  1552      // 768 + 768 + 16
#define HID    512

// -------- scratch (device globals; no allocation allowed) --------
__device__ __align__(16) float g_x[B_SZ * XCOLS];     // concatenated fc1 input
__device__ __align__(16) float g_y[B_SZ * HID];       // fc1 output (pre-BN)
__device__ __align__(16) float g_p[6][B_SZ * HID];    // GEMM partials
__device__ float g_sum[HID];                          // column sums
__device__ float g_sum2[HID];                         // column sums of squares

// =====================================================================
// Shared GEMM body: 32(M) x 128(N) tile over K [k0, k0+8*nkt) -> g_p[z]
// 64 working threads (t < 64); ALL threads in the block must call this
// (they participate in the barriers). Champion R11 inner loop.
// =====================================================================
__device__ __forceinline__ void gemm_tile(
    float (*As)[36], float (*Bs)[128],
    int t, int m0, int n0, int k0, int nkt,
    const float* __restrict__ W, float* __restrict__ outp)
{
    bool act = (t < 64);

    int a_r = t >> 1;
    int a_k = (t & 1) * 4;
    int b_k = t >> 4;             // 0..3 (for t<64)
    int b_n = (t & 15) * 4;       // 0..60

    const float* gA = g_x + (size_t)(m0 + (act ? a_r : 0)) * XCOLS + k0 + a_k;
    const float* gB = W + (size_t)(k0 + (act ? b_k : 0)) * HID + n0 + b_n;

    float4 pa = make_float4(0.f,0.f,0.f,0.f);
    float4 pb0 = pa, pb1 = pa, pb2 = pa, pb3 = pa;
    if (act) {
        pa  = *(const float4*)gA;
        pb0 = *(const float4*)gB;
        pb1 = *(const float4*)(gB + 64);
        pb2 = *(const float4*)(gB + 4 * HID);
        pb3 = *(const float4*)(gB + 4 * HID + 64);
    }

    int tm = t & 3;
    int tn = (t >> 2) & 15;

    unsigned long long acc[8][4] = {};

    for (int kt = 0; kt < nkt; kt++) {
        __syncthreads();
        if (act) {
            As[a_k + 0][a_r] = pa.x;
            As[a_k + 1][a_r] = pa.y;
            As[a_k + 2][a_r] = pa.z;
            As[a_k + 3][a_r] = pa.w;
            *(float4*)&Bs[b_k    ][b_n]      = pb0;
            *(float4*)&Bs[b_k    ][b_n + 64] = pb1;
            *(float4*)&Bs[b_k + 4][b_n]      = pb2;
            *(float4*)&Bs[b_k + 4][b_n + 64] = pb3;
        }
        __syncthreads();

        if (act && kt + 1 < nkt) {
            const float* nA = gA + (size_t)(kt + 1) * 8;
            const float* nB = gB + (size_t)(kt + 1) * 8 * HID;
            pa  = *(const float4*)nA;
            pb0 = *(const float4*)nB;
            pb1 = *(const float4*)(nB + 64);
            pb2 = *(const float4*)(nB + 4 * HID);
            pb3 = *(const float4*)(nB + 4 * HID + 64);
        }

        if (act) {
            #pragma unroll
            for (int k = 0; k < 8; k++) {
                ulonglong2 b01 = *(const ulonglong2*)&Bs[k][tn * 8];
                ulonglong2 b23 = *(const ulonglong2*)&Bs[k][tn * 8 + 4];
                float4 a0 = *(const float4*)&As[k][tm * 8];
                float4 a1 = *(const float4*)&As[k][tm * 8 + 4];
                float am[8] = {a0.x, a0.y, a0.z, a0.w, a1.x, a1.y, a1.z, a1.w};
                #pragma unroll
                for (int m = 0; m < 8; m++) {
                    unsigned int av = __float_as_uint(am[m]);
                    unsigned long long ad;
                    asm("mov.b64 %0, {%1, %1};" : "=l"(ad) : "r"(av));
                    asm("fma.rn.f32x2 %0, %1, %2, %0;" : "+l"(acc[m][0]) : "l"(ad), "l"(b01.x));
                    asm("fma.rn.f32x2 %0, %1, %2, %0;" : "+l"(acc[m][1]) : "l"(ad), "l"(b01.y));
                    asm("fma.rn.f32x2 %0, %1, %2, %0;" : "+l"(acc[m][2]) : "l"(ad), "l"(b23.x));
                    asm("fma.rn.f32x2 %0, %1, %2, %0;" : "+l"(acc[m][3]) : "l"(ad), "l"(b23.y));
                }
            }
        }
    }

    if (act) {
        #pragma unroll
        for (int m = 0; m < 8; m++) {
            int row = m0 + tm * 8 + m;
            int col = n0 + tn * 8;
            float4 v0, v1;
            v0.x = __uint_as_float((unsigned int)(acc[m][0]));
            v0.y = __uint_as_float((unsigned int)(acc[m][0] >> 32));
            v0.z = __uint_as_float((unsigned int)(acc[m][1]));
            v0.w = __uint_as_float((unsigned int)(acc[m][1] >> 32));
            v1.x = __uint_as_float((unsigned int)(acc[m][2]));
            v1.y = __uint_as_float((unsigned int)(acc[m][2] >> 32));
            v1.z = __uint_as_float((unsigned int)(acc[m][3]));
            v1.w = __uint_as_float((unsigned int)(acc[m][3] >> 32));
            *(float4*)(outp + (size_t)row * HID + col)     = v0;
            *(float4*)(outp + (size_t)row * HID + col + 4) = v1;
        }
    }
}

// =====================================================================
// Mean body (champion shape): sum rows [0,len) of [len<=L, 768] tile,
// divide by len, store 768 floats at dst. 192 threads, float4 each.
// =====================================================================
__device__ __forceinline__ void mean_rows(const float* __restrict__ src,
                                          int len, float* __restrict__ dst, int t)
{
    const float4* base = (const float4*)src;
    float4 s0 = make_float4(0.f, 0.f, 0.f, 0.f);
    float4 s1 = s0, s2 = s0, s3 = s0;

    int l = 0;
    for (; l + 4 <= len; l += 4) {
        float4 v0 = base[(size_t)(l + 0) * 192 + t];
        float4 v1 = base[(size_t)(l + 1) * 192 + t];
        float4 v2 = base[(size_t)(l + 2) * 192 + t];
        float4 v3 = base[(size_t)(l + 3) * 192 + t];
        s0.x += v0.x; s0.y += v0.y; s0.z += v0.z; s0.w += v0.w;
        s1.x += v1.x; s1.y += v1.y; s1.z += v1.z; s1.w += v1.w;
        s2.x += v2.x; s2.y += v2.y; s2.z += v2.z; s2.w += v2.w;
        s3.x += v3.x; s3.y += v3.y; s3.z += v3.z; s3.w += v3.w;
    }
    for (; l < len; l++) {
        float4 v = base[(size_t)l * 192 + t];
        s0.x += v.x; s0.y += v.y; s0.z += v.z; s0.w += v.w;
    }

    float inv = 1.0f / (float)len;
    float4 r;
    r.x = ((s0.x + s1.x) + (s2.x + s3.x)) * inv;
    r.y = ((s0.y + s1.y) + (s2.y + s3.y)) * inv;
    r.z = ((s0.z + s1.z) + (s2.z + s3.z)) * inv;
    r.w = ((s0.w + s1.w) + (s2.w + s3.w)) * inv;
    *(float4*)(dst + t * 4) = r;
}

// =====================================================================
// Kernel 1: hashtag mean (blocks 0..1023) + NCF (blocks 1024..1031).
// Writes g_x cols [768,1552); zeroes g_sum/g_sum2 (block 1024).
// grid: 1032 x 192
// =====================================================================
__global__ void hash_ncf_kernel(const float* __restrict__ hf,
                                const int*   __restrict__ hl,
                                const int* __restrict__ users, const int* __restrict__ items,
                                const float* __restrict__ u_mf,  const float* __restrict__ i_mf,
                                const float* __restrict__ u_mlp, const float* __restrict__ i_mlp,
                                const float* __restrict__ w0, const float* __restrict__ b0,
                                const float* __restrict__ w1, const float* __restrict__ b1,
                                const float* __restrict__ w2, const float* __restrict__ b2)
{
    int t = threadIdx.x;
    int bid = blockIdx.x;

    if (bid < 1024) {
        int b = bid;
        mean_rows(hf + (size_t)b * LH * D_SZ, hl[b], g_x + (size_t)b * XCOLS + 768, t);
        return;
    }

    // ---- NCF path: blocks 1024..1031, threads 0..127 active for compute
    __shared__ float sw0[16 * 32], sb0[32];
    __shared__ float sw1[32 * 16], sb1[16];
    __shared__ float sw2[16 * 8],  sb2[8];

    if (bid == 1024) {
        for (int i = t; i < 512; i += 192) { g_sum[i] = 0.f; g_sum2[i] = 0.f; }
    }

    for (int i = t; i < 512; i += 192) sw0[i] = w0[i];
    for (int i = t; i < 512; i += 192) sw1[i] = w1[i];
    if (t < 128) sw2[t] = w2[t];
    if (t < 32)  sb0[t] = b0[t];
    if (t < 16)  sb1[t] = b1[t];
    if (t < 8)   sb2[t] = b2[t];
    __syncthreads();

    if (t >= 128) return;

    int b = (bid - 1024) * 128 + t;
    int u = users[b];
    int it = items[b];

    float in16[16];
    #pragma unroll
    for (int j = 0; j < 8; j++) in16[j]     = u_mlp[u * 8 + j];
    #pragma unroll
    for (int j = 0; j < 8; j++) in16[8 + j] = i_mlp[it * 8 + j];

    float h1[32];
    #pragma unroll
    for (int j = 0; j < 32; j++) {
        float s = sb0[j];
        #pragma unroll
        for (int k = 0; k < 16; k++) s += in16[k] * sw0[k * 32 + j];
        h1[j] = fmaxf(s, 0.f);
    }
    float h2[16];
    #pragma unroll
    for (int j = 0; j < 16; j++) {
        float s = sb1[j];
        #pragma unroll
        for (int k = 0; k < 32; k++) s += h1[k] * sw1[k * 16 + j];
        h2[j] = fmaxf(s, 0.f);
    }
    float* xp = g_x + (size_t)b * XCOLS + 1536;
    #pragma unroll
    for (int j = 0; j < 8; j++) {
        float s = sb2[j];
        #pragma unroll
        for (int k = 0; k < 16; k++) s += h2[k] * sw2[k * 8 + j];
        xp[j] = fmaxf(s, 0.f);
    }
    #pragma unroll
    for (int j = 0; j < 8; j++) {
        xp[8 + j] = u_mf[u * 8 + j] * i_mf[it * 8 + j];
    }
}

// =====================================================================
// Kernel 2: FUSED user-mean + overlap-GEMM.
// blocks [0,256): GEMM over K [768,1552) (hashtag/ncf cols, ready),
//   split-K=2: z'=0 -> K [768,1160) -> g_p[4]; z'=1 -> [1160,1552) -> g_p[5]
//   (49 k-tiles each; only t<64 work, all 192 threads hit barriers)
// blocks [256,1280): user mean, one block per sample -> g_x[b][0:768]
// grid: 1280 x 192
// =====================================================================
__global__ void user_gemm_kernel(const float* __restrict__ uf,
                                 const int*   __restrict__ ul,
                                 const float* __restrict__ W)
{
    __shared__ __align__(16) float As[8][36];
    __shared__ __align__(16) float Bs[8][128];

    int t = threadIdx.x;
    int bid = blockIdx.x;

    if (bid < 256) {
        int zz = bid & 1;                 // 0/1
        int ny = (bid >> 1) & 3;
        int mx = bid >> 3;                // 0..31
        int k0 = 768 + zz * 392;
        gemm_tile(As, Bs, t, mx * 32, ny * 128, k0, 49, W, g_p[4 + zz]);
        return;
    }

    int b = bid - 256;
    mean_rows(uf + (size_t)b * LU * D_SZ, ul[b], g_x + (size_t)b * XCOLS, t);
}

// =====================================================================
// Kernel 3: post-GEMM over K [0,768) (user cols), split-K=4 x 192.
// grid: (32, 4, 4) x 64   -> g_p[0..3]
// =====================================================================
__global__ void __launch_bounds__(64) post_gemm_kernel(const float* __restrict__ W)
{
    __shared__ __align__(16) float As[8][36];
    __shared__ __align__(16) float Bs[8][128];

    int z = blockIdx.z;
    gemm_tile(As, Bs, threadIdx.x, blockIdx.x * 32, blockIdx.y * 128,
              z * 192, 24, W, g_p[z]);
}

// =====================================================================
// Kernel 4: combine 6 partials -> g_y, accumulate BN sums (atomics).
// grid: 256 blocks x 512 threads, 4 rows per block
// =====================================================================
__global__ void bn_combine_kernel()
{
    int c  = threadIdx.x;
    int r0 = blockIdx.x * 4;

    float s = 0.f, s2 = 0.f;
    #pragma unroll
    for (int i = 0; i < 4; i++) {
        size_t idx = (size_t)(r0 + i) * HID + c;
        float v = ((g_p[0][idx] + g_p[1][idx]) + (g_p[2][idx] + g_p[3][idx]))
                + (g_p[4][idx] + g_p[5][idx]);
        g_y[idx] = v;
        s  += v;
        s2 += v * v;
    }
    atomicAdd(&g_sum[c],  s);
    atomicAdd(&g_sum2[c], s2);
}

// =====================================================================
// Kernel 5: out[b] = sigmoid( relu(y*a + c) . fc3_w + fc3_b )
// grid: 128 blocks x 256 threads (1 warp per batch row)
// =====================================================================
__global__ void final_kernel(const float* __restrict__ gamma,
                             const float* __restrict__ beta,
                             const float* __restrict__ fc3_w,
                             const float* __restrict__ fc3_b,
                             float* __restrict__ out)
{
    __shared__ float sa[HID];
    __shared__ float sc[HID];

    int t = threadIdx.x;
    #pragma unroll
    for (int i = 0; i < 2; i++) {
        int ch = t + i * 256;
        float s1 = g_sum[ch];
        float s2 = g_sum2[ch];
        float m   = s1 * (1.0f / (float)B_SZ);
        float var = s2 * (1.0f / (float)B_SZ) - m * m;
        float a   = gamma[ch] * rsqrtf(var + 1e-5f);
        sa[ch] = a;
        sc[ch] = beta[ch] - m * a;
    }
    __syncthreads();

    int warp = t >> 5;
    int lane = t & 31;
    int b = blockIdx.x * 8 + warp;

    const float* yrow = g_y + (size_t)b * HID;
    float s = 0.f;
    #pragma unroll
    for (int i = 0; i < HID / 32; i++) {
        int ch = lane + i * 32;
        float v = fmaf(yrow[ch], sa[ch], sc[ch]);
        v = fmaxf(v, 0.f);
        s = fmaf(v, fc3_w[ch], s);
    }
    #pragma unroll
    for (int o = 16; o > 0; o >>= 1)
        s += __shfl_xor_sync(0xFFFFFFFFu, s, o);

    if (lane == 0) {
        float z = s + fc3_b[0];
        out[b] = 1.0f / (1.0f + expf(-z));
    }
}

// =====================================================================
// Launch
// =====================================================================
extern "C" void kernel_launch(void* const* d_in, const int* in_sizes, int n_in,
                              void* d_out, int out_size)
{
    const float* uf     = (const float*)d_in[1];
    const int*   ul     = (const int*)  d_in[2];
    const float* hf     = (const float*)d_in[3];
    const int*   hl     = (const int*)  d_in[4];
    const int*   users  = (const int*)  d_in[5];
    const int*   items  = (const int*)  d_in[6];
    const float* fc1_w  = (const float*)d_in[7];
    const float* gamma  = (const float*)d_in[9];
    const float* beta   = (const float*)d_in[10];
    const float* fc3_w  = (const float*)d_in[11];
    const float* fc3_b  = (const float*)d_in[12];
    const float* u_mf   = (const float*)d_in[13];
    const float* i_mf   = (const float*)d_in[14];
    const float* u_mlp  = (const float*)d_in[15];
    const float* i_mlp  = (const float*)d_in[16];
    const float* w0     = (const float*)d_in[17];
    const float* b0     = (const float*)d_in[18];
    const float* w1     = (const float*)d_in[19];
    const float* b1     = (const float*)d_in[20];
    const float* w2     = (const float*)d_in[21];
    const float* b2     = (const float*)d_in[22];
    float* out = (float*)d_out;

    hash_ncf_kernel<<<1032, 192>>>(hf, hl, users, items, u_mf, i_mf, u_mlp, i_mlp,
                                   w0, b0, w1, b1, w2, b2);
    user_gemm_kernel<<<1280, 192>>>(uf, ul, fc1_w);
    post_gemm_kernel<<<dim3(32, 4, 4), 64>>>(fc1_w);
    bn_combine_kernel<<<256, 512>>>();
    final_kernel<<<128, 256>>>(gamma, beta, fc3_w, fc3_b, out);
}